// round 1
// baseline (speedup 1.0000x reference)
#include <cuda_runtime.h>
#include <cstdint>

#define THREADS 256
#define FDIM 64
#define EDIM 32

// ---- f32x2 packed helpers (Blackwell FFMA2 path, PTX-only) ----
static __device__ __forceinline__ unsigned long long pk2(float lo, float hi) {
    unsigned long long r;
    asm("mov.b64 %0, {%1, %2};" : "=l"(r) : "f"(lo), "f"(hi));
    return r;
}
static __device__ __forceinline__ float2 upk2(unsigned long long v) {
    float2 r;
    asm("mov.b64 {%0, %1}, %2;" : "=f"(r.x), "=f"(r.y) : "l"(v));
    return r;
}
static __device__ __forceinline__ unsigned long long mul2(unsigned long long a, unsigned long long b) {
    unsigned long long d;
    asm("mul.rn.f32x2 %0, %1, %2;" : "=l"(d) : "l"(a), "l"(b));
    return d;
}
static __device__ __forceinline__ unsigned long long fma2_(unsigned long long a, unsigned long long b, unsigned long long c) {
    unsigned long long d;
    asm("fma.rn.f32x2 %0, %1, %2, %3;" : "=l"(d) : "l"(a), "l"(b), "l"(c));
    return d;
}

__global__ void __launch_bounds__(THREADS)
afm_kernel(const float* __restrict__ x,
           const float* __restrict__ attn_w,
           const float* __restrict__ attn_b,
           const float* __restrict__ attn_h,
           const float* __restrict__ pool_w,
           const float* __restrict__ pool_b,
           float* __restrict__ out)
{
    __shared__ float xt[EDIM][68];   // x transposed, padded: row = feature index f
    __shared__ float w5[EDIM][8];    // [e][0..3]=attn_w, [e][4]=pool_w
    __shared__ float rmax[8], rse[8], rsq[8];
    __shared__ float bmax;

    const int t = threadIdx.x;
    const int b = blockIdx.x;
    const float* xb = x + (size_t)b * (FDIM * EDIM);

    // ---- load + transpose x[b]: 2048 floats, 512 float4, 2 per thread ----
    #pragma unroll
    for (int k = 0; k < 2; k++) {
        int q  = t + k * THREADS;      // float4 index 0..511
        int f  = q >> 3;               // 8 float4 per feature row (E=32)
        int e4 = q & 7;
        float4 v = reinterpret_cast<const float4*>(xb)[q];
        xt[e4 * 4 + 0][f] = v.x;
        xt[e4 * 4 + 1][f] = v.y;
        xt[e4 * 4 + 2][f] = v.z;
        xt[e4 * 4 + 3][f] = v.w;
    }
    if (t < EDIM) {
        float4 wv = reinterpret_cast<const float4*>(attn_w)[t];  // attn_w[e][0..3]
        w5[t][0] = wv.x; w5[t][1] = wv.y; w5[t][2] = wv.z; w5[t][3] = wv.w;
        w5[t][4] = pool_w[t];
    }
    __syncthreads();

    // ---- per-thread 4x4 (i,j) tile, 5 heads, f32x2-packed accumulators ----
    const int ti = t >> 4, tj = t & 15;
    const int i0 = ti * 4, j0 = tj * 4;

    unsigned long long acc[5][4][2];
    #pragma unroll
    for (int a = 0; a < 5; a++)
        #pragma unroll
        for (int ii = 0; ii < 4; ii++)
            #pragma unroll
            for (int jp = 0; jp < 2; jp++)
                acc[a][ii][jp] = 0ull;

    #pragma unroll 4
    for (int e = 0; e < EDIM; e++) {
        float4 xi = *reinterpret_cast<const float4*>(&xt[e][i0]);
        float4 xj = *reinterpret_cast<const float4*>(&xt[e][j0]);
        float4 wv = *reinterpret_cast<const float4*>(&w5[e][0]);
        float  wp = w5[e][4];

        unsigned long long xj01 = pk2(xj.x, xj.y);
        unsigned long long xj23 = pk2(xj.z, xj.w);
        unsigned long long dw[5] = { pk2(wv.x, wv.x), pk2(wv.y, wv.y),
                                     pk2(wv.z, wv.z), pk2(wv.w, wv.w),
                                     pk2(wp,   wp) };
        float xia[4] = {xi.x, xi.y, xi.z, xi.w};

        #pragma unroll
        for (int ii = 0; ii < 4; ii++) {
            unsigned long long dxi = pk2(xia[ii], xia[ii]);
            #pragma unroll
            for (int a = 0; a < 5; a++) {
                unsigned long long c = mul2(dxi, dw[a]);
                acc[a][ii][0] = fma2_(c, xj01, acc[a][ii][0]);
                acc[a][ii][1] = fma2_(c, xj23, acc[a][ii][1]);
            }
        }
    }

    // ---- combine: relu-MLP score s, pooled bilinear q per pair ----
    const float b0 = attn_b[0], b1 = attn_b[1], b2 = attn_b[2], b3 = attn_b[3];
    const float h0 = attn_h[0], h1 = attn_h[1], h2 = attn_h[2], h3 = attn_h[3];

    float sc[4][4], qc[4][4];
    #pragma unroll
    for (int ii = 0; ii < 4; ii++) {
        #pragma unroll
        for (int jp = 0; jp < 2; jp++) {
            float2 a0 = upk2(acc[0][ii][jp]);
            float2 a1 = upk2(acc[1][ii][jp]);
            float2 a2 = upk2(acc[2][ii][jp]);
            float2 a3 = upk2(acc[3][ii][jp]);
            float2 a4 = upk2(acc[4][ii][jp]);
            sc[ii][jp * 2 + 0] = fmaxf(a0.x + b0, 0.f) * h0 + fmaxf(a1.x + b1, 0.f) * h1
                               + fmaxf(a2.x + b2, 0.f) * h2 + fmaxf(a3.x + b3, 0.f) * h3;
            sc[ii][jp * 2 + 1] = fmaxf(a0.y + b0, 0.f) * h0 + fmaxf(a1.y + b1, 0.f) * h1
                               + fmaxf(a2.y + b2, 0.f) * h2 + fmaxf(a3.y + b3, 0.f) * h3;
            qc[ii][jp * 2 + 0] = a4.x;
            qc[ii][jp * 2 + 1] = a4.y;
        }
    }

    // ---- softmax over upper triangle (i < j), fused weighted scalar sum ----
    float lmax = -1e30f;
    #pragma unroll
    for (int ii = 0; ii < 4; ii++)
        #pragma unroll
        for (int jj = 0; jj < 4; jj++)
            if (i0 + ii < j0 + jj) lmax = fmaxf(lmax, sc[ii][jj]);

    #pragma unroll
    for (int o = 16; o; o >>= 1)
        lmax = fmaxf(lmax, __shfl_xor_sync(0xffffffffu, lmax, o));
    if ((t & 31) == 0) rmax[t >> 5] = lmax;
    __syncthreads();
    if (t == 0) {
        float m = rmax[0];
        #pragma unroll
        for (int i = 1; i < 8; i++) m = fmaxf(m, rmax[i]);
        bmax = m;
    }
    __syncthreads();
    const float m = bmax;

    float se = 0.f, sq = 0.f;
    #pragma unroll
    for (int ii = 0; ii < 4; ii++)
        #pragma unroll
        for (int jj = 0; jj < 4; jj++)
            if (i0 + ii < j0 + jj) {
                float ex = __expf(sc[ii][jj] - m);
                se += ex;
                sq += ex * qc[ii][jj];
            }

    #pragma unroll
    for (int o = 16; o; o >>= 1) {
        se += __shfl_xor_sync(0xffffffffu, se, o);
        sq += __shfl_xor_sync(0xffffffffu, sq, o);
    }
    if ((t & 31) == 0) { rse[t >> 5] = se; rsq[t >> 5] = sq; }
    __syncthreads();
    if (t == 0) {
        float S = 0.f, Q = 0.f;
        #pragma unroll
        for (int i = 0; i < 8; i++) { S += rse[i]; Q += rsq[i]; }
        out[b] = Q / S + pool_b[0];
    }
}

extern "C" void kernel_launch(void* const* d_in, const int* in_sizes, int n_in,
                              void* d_out, int out_size)
{
    const float* x      = (const float*)d_in[0];
    const float* attn_w = (const float*)d_in[1];
    const float* attn_b = (const float*)d_in[2];
    const float* attn_h = (const float*)d_in[3];
    const float* pool_w = (const float*)d_in[4];
    const float* pool_b = (const float*)d_in[5];
    float* out = (float*)d_out;

    int B = in_sizes[0] / (FDIM * EDIM);
    afm_kernel<<<B, THREADS>>>(x, attn_w, attn_b, attn_h, pool_w, pool_b, out);
}

// round 2
// speedup vs baseline: 1.0053x; 1.0053x over previous
#include <cuda_runtime.h>
#include <cstdint>

#define THREADS 160
#define NTILE   136       // 16*17/2 upper-triangle 4x4 tiles
#define FDIM    64
#define EDIM    32

// dynamic smem layout (floats):
//   xt2 : EDIM * 128   = 4096  floats   (x duplicated pairs: xt2[e][2f],[2f+1] = x[f,e])
//   y   : 5*EDIM*FDIM  = 10240 floats   (y[(a*32+e)*64 + f] = x[f,e] * w5[e][a])
#define XT2_FLOATS (EDIM * 128)
#define Y_FLOATS   (5 * EDIM * FDIM)
#define SMEM_BYTES ((XT2_FLOATS + Y_FLOATS) * 4)

// ---- f32x2 packed helpers ----
static __device__ __forceinline__ unsigned long long pk2(float lo, float hi) {
    unsigned long long r;
    asm("mov.b64 %0, {%1, %2};" : "=l"(r) : "f"(lo), "f"(hi));
    return r;
}
static __device__ __forceinline__ float2 upk2(unsigned long long v) {
    float2 r;
    asm("mov.b64 {%0, %1}, %2;" : "=f"(r.x), "=f"(r.y) : "l"(v));
    return r;
}
static __device__ __forceinline__ unsigned long long fma2_(unsigned long long a, unsigned long long b, unsigned long long c) {
    unsigned long long d;
    asm("fma.rn.f32x2 %0, %1, %2, %3;" : "=l"(d) : "l"(a), "l"(b), "l"(c));
    return d;
}

__global__ void __launch_bounds__(THREADS)
afm_kernel(const float* __restrict__ x,
           const float* __restrict__ attn_w,
           const float* __restrict__ attn_b,
           const float* __restrict__ attn_h,
           const float* __restrict__ pool_w,
           const float* __restrict__ pool_b,
           float* __restrict__ out)
{
    extern __shared__ __align__(16) float sm[];
    float* Xt2 = sm;                 // [EDIM][128]
    float* Y   = sm + XT2_FLOATS;    // [5*EDIM][64]

    __shared__ float w5[EDIM][8];    // [e][0..3]=attn_w, [e][4]=pool_w
    __shared__ float rmax[5], rse[5], rsq[5];
    __shared__ float bmax;

    const int t = threadIdx.x;
    const int b = blockIdx.x;
    const float* xb = x + (size_t)b * (FDIM * EDIM);

    // ---- load + transpose x[b] into duplicated-pair layout ----
    // 512 float4 total; xt2 as ull: index (e*64 + f)
    unsigned long long* Xt2u = reinterpret_cast<unsigned long long*>(Xt2);
    for (int q = t; q < 512; q += THREADS) {
        int f  = q >> 3;            // feature row 0..63
        int e4 = q & 7;             // group of 4 e's
        float4 v = reinterpret_cast<const float4*>(xb)[q];
        Xt2u[(e4 * 4 + 0) * 64 + f] = pk2(v.x, v.x);
        Xt2u[(e4 * 4 + 1) * 64 + f] = pk2(v.y, v.y);
        Xt2u[(e4 * 4 + 2) * 64 + f] = pk2(v.z, v.z);
        Xt2u[(e4 * 4 + 3) * 64 + f] = pk2(v.w, v.w);
    }
    if (t < EDIM) {
        float4 wv = reinterpret_cast<const float4*>(attn_w)[t];  // attn_w[e][0..3]
        w5[t][0] = wv.x; w5[t][1] = wv.y; w5[t][2] = wv.z; w5[t][3] = wv.w;
        w5[t][4] = pool_w[t];
    }
    __syncthreads();

    // ---- build y[a][e][f] = x[f,e] * w5[e][a]  (2560 float4 stores) ----
    for (int q = t; q < (5 * EDIM * FDIM) / 4; q += THREADS) {
        int f4  = q & 15;             // float4 within row
        int row = q >> 4;             // a*32 + e
        int e   = row & 31;
        int a   = row >> 5;
        int f0  = f4 * 4;
        float4 u0 = *reinterpret_cast<const float4*>(Xt2 + e * 128 + 2 * f0);      // x0,x0,x1,x1
        float4 u1 = *reinterpret_cast<const float4*>(Xt2 + e * 128 + 2 * f0 + 4);  // x2,x2,x3,x3
        float  w  = w5[e][a];
        float4 o  = make_float4(u0.x * w, u0.z * w, u1.x * w, u1.z * w);
        *reinterpret_cast<float4*>(Y + row * 64 + f0) = o;
    }
    __syncthreads();

    // ---- map thread -> upper-triangle tile (ti <= tj), 4x4 cells ----
    int k = (t < NTILE) ? t : (NTILE - 1);
    int ti = (int)((33.0f - sqrtf(1089.0f - 8.0f * (float)k)) * 0.5f);
    // fix float rounding
    while (ti > 0 && (33 * ti - ti * ti) / 2 > k) ti--;
    while ((33 * (ti + 1) - (ti + 1) * (ti + 1)) / 2 <= k) ti++;
    int tj = ti + (k - (33 * ti - ti * ti) / 2);
    const int i0 = ti * 4, j0 = tj * 4;

    // ---- mainloop: 5-head bilinear accum over e, 4x4 tile, f32x2 packed ----
    unsigned long long acc[5][4][2];
    #pragma unroll
    for (int a = 0; a < 5; a++)
        #pragma unroll
        for (int ii = 0; ii < 4; ii++) { acc[a][ii][0] = 0ull; acc[a][ii][1] = 0ull; }

    #pragma unroll 2
    for (int e = 0; e < EDIM; e++) {
        ulonglong2 dxa = *reinterpret_cast<const ulonglong2*>(Xt2 + e * 128 + 2 * i0);
        ulonglong2 dxb = *reinterpret_cast<const ulonglong2*>(Xt2 + e * 128 + 2 * i0 + 4);
        unsigned long long dxi[4] = { dxa.x, dxa.y, dxb.x, dxb.y };
        #pragma unroll
        for (int a = 0; a < 5; a++) {
            ulonglong2 yv = *reinterpret_cast<const ulonglong2*>(Y + (a * EDIM + e) * FDIM + j0);
            #pragma unroll
            for (int ii = 0; ii < 4; ii++) {
                acc[a][ii][0] = fma2_(dxi[ii], yv.x, acc[a][ii][0]);
                acc[a][ii][1] = fma2_(dxi[ii], yv.y, acc[a][ii][1]);
            }
        }
    }

    // ---- combine: relu-MLP score, pooled bilinear per pair ----
    const float b0 = attn_b[0], b1 = attn_b[1], b2 = attn_b[2], b3 = attn_b[3];
    const float h0 = attn_h[0], h1 = attn_h[1], h2 = attn_h[2], h3 = attn_h[3];

    float sc[4][4], qc[4][4];
    #pragma unroll
    for (int ii = 0; ii < 4; ii++) {
        #pragma unroll
        for (int jp = 0; jp < 2; jp++) {
            float2 a0 = upk2(acc[0][ii][jp]);
            float2 a1 = upk2(acc[1][ii][jp]);
            float2 a2 = upk2(acc[2][ii][jp]);
            float2 a3 = upk2(acc[3][ii][jp]);
            float2 a4 = upk2(acc[4][ii][jp]);
            sc[ii][jp * 2 + 0] = fmaxf(a0.x + b0, 0.f) * h0 + fmaxf(a1.x + b1, 0.f) * h1
                               + fmaxf(a2.x + b2, 0.f) * h2 + fmaxf(a3.x + b3, 0.f) * h3;
            sc[ii][jp * 2 + 1] = fmaxf(a0.y + b0, 0.f) * h0 + fmaxf(a1.y + b1, 0.f) * h1
                               + fmaxf(a2.y + b2, 0.f) * h2 + fmaxf(a3.y + b3, 0.f) * h3;
            qc[ii][jp * 2 + 0] = a4.x;
            qc[ii][jp * 2 + 1] = a4.y;
        }
    }

    const bool live = (t < NTILE);

    // ---- softmax over i<j cells, fused weighted scalar sum ----
    float lmax = -1e30f;
    #pragma unroll
    for (int ii = 0; ii < 4; ii++)
        #pragma unroll
        for (int jj = 0; jj < 4; jj++)
            if (live && (i0 + ii < j0 + jj)) lmax = fmaxf(lmax, sc[ii][jj]);

    #pragma unroll
    for (int o = 16; o; o >>= 1)
        lmax = fmaxf(lmax, __shfl_xor_sync(0xffffffffu, lmax, o));
    if ((t & 31) == 0) rmax[t >> 5] = lmax;
    __syncthreads();
    if (t == 0) {
        float m = rmax[0];
        #pragma unroll
        for (int i = 1; i < 5; i++) m = fmaxf(m, rmax[i]);
        bmax = m;
    }
    __syncthreads();
    const float m = bmax;

    float se = 0.f, sq = 0.f;
    #pragma unroll
    for (int ii = 0; ii < 4; ii++)
        #pragma unroll
        for (int jj = 0; jj < 4; jj++)
            if (live && (i0 + ii < j0 + jj)) {
                float ex = __expf(sc[ii][jj] - m);
                se += ex;
                sq += ex * qc[ii][jj];
            }

    #pragma unroll
    for (int o = 16; o; o >>= 1) {
        se += __shfl_xor_sync(0xffffffffu, se, o);
        sq += __shfl_xor_sync(0xffffffffu, sq, o);
    }
    if ((t & 31) == 0) { rse[t >> 5] = se; rsq[t >> 5] = sq; }
    __syncthreads();
    if (t == 0) {
        float S = 0.f, Q = 0.f;
        #pragma unroll
        for (int i = 0; i < 5; i++) { S += rse[i]; Q += rsq[i]; }
        out[b] = Q / S + pool_b[0];
    }
}

extern "C" void kernel_launch(void* const* d_in, const int* in_sizes, int n_in,
                              void* d_out, int out_size)
{
    const float* x      = (const float*)d_in[0];
    const float* attn_w = (const float*)d_in[1];
    const float* attn_b = (const float*)d_in[2];
    const float* attn_h = (const float*)d_in[3];
    const float* pool_w = (const float*)d_in[4];
    const float* pool_b = (const float*)d_in[5];
    float* out = (float*)d_out;

    cudaFuncSetAttribute(afm_kernel, cudaFuncAttributeMaxDynamicSharedMemorySize, SMEM_BYTES);

    int B = in_sizes[0] / (FDIM * EDIM);
    afm_kernel<<<B, THREADS, SMEM_BYTES>>>(x, attn_w, attn_b, attn_h, pool_w, pool_b, out);
}